// round 4
// baseline (speedup 1.0000x reference)
#include <cuda_runtime.h>
#include <math.h>
#include <stdint.h>

#define TOK   2048
#define HD    1024
#define ID    1024
#define NE    32
#define TOPK  4
#define TWOI  2048
#define PAIRS (TOK*TOPK)
#define LIMITF 7.0f
#define ALPHAF 1.702f

// -------- device scratch --------
__device__ int   g_count[NE];
__device__ int   g_offset[NE];
__device__ int   g_cursor[NE];
__device__ int   g_topk_idx[TOK * TOPK];
__device__ float g_topk_w[TOK * TOPK];
__device__ int   g_pair_token[PAIRS];
__device__ int   g_pair_of[TOK * TOPK];
__device__ float g_act[(size_t)PAIRS * ID];
__device__ float g_y[(size_t)PAIRS * HD];

// -------- helpers --------
__device__ __forceinline__ float tfr(float x) {   // round fp32 -> tf32 (rna), keep fp32 container
    unsigned r;
    asm("cvt.rna.tf32.f32 %0, %1;" : "=r"(r) : "f"(x));
    return __uint_as_float(r);
}

__device__ __forceinline__ void mma_tf32(float* d, const unsigned* a, const unsigned* b) {
    asm volatile(
        "mma.sync.aligned.m16n8k8.row.col.f32.tf32.tf32.f32 "
        "{%0,%1,%2,%3}, {%4,%5,%6,%7}, {%8,%9}, {%0,%1,%2,%3};\n"
        : "+f"(d[0]), "+f"(d[1]), "+f"(d[2]), "+f"(d[3])
        : "r"(a[0]), "r"(a[1]), "r"(a[2]), "r"(a[3]),
          "r"(b[0]), "r"(b[1]));
}

// smem word layout (floats): A0 @0 (128*18), A1 @2304, B0 @4608 (16*260), B1 @8768
#define AW      2304
#define BW      4160
#define B_BASE  4608
#define SMEM_BYTES ((B_BASE + 2*BW) * 4)   // 51712

// -------- tcgen05-free tf32 grouped GEMM (both stages) --------
// Block tile 128(M) x 256(N), BK=16, 512 threads, warp tile 32x64.
template<bool FIRST>
__global__ __launch_bounds__(512) void moe_gemm(const float* __restrict__ x,
                                                const float* __restrict__ W,
                                                const float* __restrict__ gub) {
    const int LDBW = FIRST ? TWOI : HD;
    const int bx = blockIdx.x;
    const int e  = blockIdx.y >> 4;
    const int rt = blockIdx.y & 15;
    const int base = g_offset[e];
    const int cnt  = g_count[e];
    const int row0 = rt * 128;
    if (row0 >= cnt) return;

    extern __shared__ float smf[];

    const int tid  = threadIdx.x;
    const int lane = tid & 31;
    const int wid  = tid >> 5;          // 0..15
    const int wm   = wid >> 2;          // 0..3
    const int wn   = wid & 3;           // 0..3
    const int lr   = lane >> 2;         // 0..7
    const int lc   = lane & 3;          // 0..3

    // ---- A staging: 1 float4 per thread per ktile ----
    const int mA = tid >> 2;            // 0..127
    const int qa = tid & 3;             // k-quad 0..3 (k = qa*4 .. qa*4+3)
    int ar = row0 + mA; if (ar >= cnt) ar = cnt - 1;
    const float* aRow;
    if (FIRST) aRow = x + (size_t)g_pair_token[base + ar] * HD + qa * 4;
    else       aRow = (const float*)g_act + (size_t)(base + ar) * ID + qa * 4;
    // permuted A word: m*18 + 8*(k>>3) + 2*(k&3) + ((k>>2)&1);  k = qa*4 + j
    const int aw = mA * 18 + 8 * (qa >> 1) + (qa & 1);

    // ---- B staging: 2 float4 per thread per ktile ----
    const int kB = tid >> 5;            // 0..15
    const int cB = tid & 31;            // n octet 0..31
    const float* bRow = W + ((size_t)e * 1024 + kB) * LDBW + bx * 256 + cB * 8;
    const int bw = kB * 260 + cB * 8;

    float acc[2][8][4];
    #pragma unroll
    for (int i = 0; i < 2; i++)
        #pragma unroll
        for (int j = 0; j < 8; j++)
            #pragma unroll
            for (int q = 0; q < 4; q++) acc[i][j][q] = 0.f;

    // ---- prologue: tile 0 -> buf 0 ----
    {
        float4 ra  = *(const float4*)aRow;
        float4 rb0 = *(const float4*)bRow;
        float4 rb1 = *(const float4*)(bRow + 4);
        float* An = smf;
        float* Bn = smf + B_BASE;
        An[aw + 0] = tfr(ra.x); An[aw + 2] = tfr(ra.y);
        An[aw + 4] = tfr(ra.z); An[aw + 6] = tfr(ra.w);
        float4 w0 = make_float4(tfr(rb0.x), tfr(rb0.y), tfr(rb0.z), tfr(rb0.w));
        float4 w1 = make_float4(tfr(rb1.x), tfr(rb1.y), tfr(rb1.z), tfr(rb1.w));
        *(float4*)&Bn[bw]     = w0;
        *(float4*)&Bn[bw + 4] = w1;
    }
    __syncthreads();

    const int NK = 64;   // 1024 / 16
    #pragma unroll 1
    for (int kt = 0; kt < NK; kt++) {
        // prefetch next tile into registers
        float4 ra, rb0, rb1;
        if (kt + 1 < NK) {
            ra  = *(const float4*)(aRow + (kt + 1) * 16);
            const float* bp = bRow + (size_t)(kt + 1) * 16 * LDBW;
            rb0 = *(const float4*)bp;
            rb1 = *(const float4*)(bp + 4);
        }

        const float* Ab = smf + (kt & 1) * AW;
        const float* Bb = smf + B_BASE + (kt & 1) * BW;

        #pragma unroll
        for (int kk = 0; kk < 2; kk++) {
            unsigned af[2][4];
            #pragma unroll
            for (int mt = 0; mt < 2; mt++) {
                const int R = wm * 32 + mt * 16 + lr;
                float2 t0 = *(const float2*)&Ab[R * 18 + kk * 8 + 2 * lc];
                float2 t1 = *(const float2*)&Ab[(R + 8) * 18 + kk * 8 + 2 * lc];
                af[mt][0] = __float_as_uint(t0.x);
                af[mt][1] = __float_as_uint(t1.x);
                af[mt][2] = __float_as_uint(t0.y);
                af[mt][3] = __float_as_uint(t1.y);
            }
            #pragma unroll
            for (int nt = 0; nt < 8; nt++) {
                const int nB = wn * 64 + nt * 8 + lr;
                unsigned bf[2];
                bf[0] = __float_as_uint(Bb[(kk * 8 + lc) * 260 + nB]);
                bf[1] = __float_as_uint(Bb[(kk * 8 + lc + 4) * 260 + nB]);
                mma_tf32(acc[0][nt], af[0], bf);
                mma_tf32(acc[1][nt], af[1], bf);
            }
        }

        if (kt + 1 < NK) {
            float* An = smf + ((kt + 1) & 1) * AW;
            float* Bn = smf + B_BASE + ((kt + 1) & 1) * BW;
            An[aw + 0] = tfr(ra.x); An[aw + 2] = tfr(ra.y);
            An[aw + 4] = tfr(ra.z); An[aw + 6] = tfr(ra.w);
            float4 w0 = make_float4(tfr(rb0.x), tfr(rb0.y), tfr(rb0.z), tfr(rb0.w));
            float4 w1 = make_float4(tfr(rb1.x), tfr(rb1.y), tfr(rb1.z), tfr(rb1.w));
            *(float4*)&Bn[bw]     = w0;
            *(float4*)&Bn[bw + 4] = w1;
        }
        __syncthreads();
    }

    // ---- epilogue ----
    if (FIRST) {
        const float* gb = gub + (size_t)e * TWOI;
        #pragma unroll
        for (int mt = 0; mt < 2; mt++) {
            #pragma unroll
            for (int half = 0; half < 2; half++) {
                const int grow = row0 + wm * 32 + mt * 16 + lr + half * 8;
                if (grow < cnt) {
                    float* orow = g_act + (size_t)(base + grow) * ID;
                    #pragma unroll
                    for (int nt = 0; nt < 8; nt++) {
                        const int i = bx * 128 + wn * 32 + nt * 4 + lc;
                        float gate = acc[mt][nt][half * 2 + 0] + gb[2 * i];
                        float up   = acc[mt][nt][half * 2 + 1] + gb[2 * i + 1];
                        gate = fminf(gate, LIMITF);
                        up   = fminf(fmaxf(up, -LIMITF), LIMITF);
                        float glu = gate / (1.f + __expf(-gate * ALPHAF));
                        orow[i] = (up + 1.f) * glu;
                    }
                }
            }
        }
    } else {
        #pragma unroll
        for (int mt = 0; mt < 2; mt++) {
            #pragma unroll
            for (int half = 0; half < 2; half++) {
                const int grow = row0 + wm * 32 + mt * 16 + lr + half * 8;
                if (grow < cnt) {
                    float* orow = g_y + (size_t)(base + grow) * HD;
                    #pragma unroll
                    for (int nt = 0; nt < 8; nt++) {
                        const int c = bx * 256 + wn * 64 + nt * 8 + 2 * lc;
                        *(float2*)(orow + c) = make_float2(acc[mt][nt][half * 2 + 0],
                                                           acc[mt][nt][half * 2 + 1]);
                    }
                }
            }
        }
    }
}

// -------- K0: reset counters --------
__global__ void reset_kernel() {
    int i = threadIdx.x;
    if (i < NE) g_count[i] = 0;
}

// -------- K1: router --------
__global__ void router_kernel(const float* __restrict__ x,
                              const float* __restrict__ rw,
                              const float* __restrict__ rb,
                              float* __restrict__ scores_out) {
    const int t    = blockIdx.x;
    const int tid  = threadIdx.x;
    const int warp = tid >> 5;
    const int lane = tid & 31;

    __shared__ float logits[NE];
    const float* xr = x + (size_t)t * HD;

    for (int e = warp; e < NE; e += 8) {
        const float* w = rw + (size_t)e * HD;
        float s = 0.f;
        for (int h = lane; h < HD; h += 32) s += xr[h] * w[h];
        #pragma unroll
        for (int off = 16; off; off >>= 1) s += __shfl_down_sync(0xffffffffu, s, off);
        if (lane == 0) logits[e] = s + rb[e];
    }
    __syncthreads();

    if (warp == 0) {
        float cur = logits[lane];
        float sel_val[TOPK];
        int   sel_idx[TOPK];
        #pragma unroll
        for (int k = 0; k < TOPK; k++) {
            float bv = cur; int bi = lane;
            #pragma unroll
            for (int off = 16; off; off >>= 1) {
                float ov = __shfl_xor_sync(0xffffffffu, bv, off);
                int   oi = __shfl_xor_sync(0xffffffffu, bi, off);
                if (ov > bv || (ov == bv && oi < bi)) { bv = ov; bi = oi; }
            }
            sel_val[k] = bv; sel_idx[k] = bi;
            if (lane == bi) cur = -1e30f;
        }
        float m = sel_val[0];
        float ex[TOPK]; float sum = 0.f;
        #pragma unroll
        for (int k = 0; k < TOPK; k++) { ex[k] = expf(sel_val[k] - m); sum += ex[k]; }
        float inv = 1.f / sum;

        float sc = 0.f;
        #pragma unroll
        for (int k = 0; k < TOPK; k++) if (lane == sel_idx[k]) sc = ex[k] * inv;
        scores_out[(size_t)t * NE + lane] = sc;

        if (lane < TOPK) {
            g_topk_idx[t * TOPK + lane] = sel_idx[lane];
            g_topk_w[t * TOPK + lane]   = ex[lane] * inv;
            atomicAdd(&g_count[sel_idx[lane]], 1);
        }
    }
}

// -------- K2: prefix sum --------
__global__ void prefix_kernel() {
    if (threadIdx.x == 0) {
        int acc = 0;
        for (int e = 0; e < NE; e++) {
            g_offset[e] = acc;
            g_cursor[e] = acc;
            acc += g_count[e];
        }
    }
}

// -------- K3: scatter --------
__global__ void scatter_kernel() {
    int t = blockIdx.x * blockDim.x + threadIdx.x;
    if (t >= TOK) return;
    #pragma unroll
    for (int k = 0; k < TOPK; k++) {
        int e   = g_topk_idx[t * TOPK + k];
        int pos = atomicAdd(&g_cursor[e], 1);
        g_pair_token[pos] = t;
        g_pair_of[t * TOPK + k] = pos;
    }
}

// -------- K7: weighted combine + down bias --------
__global__ void combine_kernel(const float* __restrict__ db,
                               float* __restrict__ out) {
    size_t idx = (size_t)blockIdx.x * blockDim.x + threadIdx.x;
    if (idx >= (size_t)TOK * HD) return;
    int t = (int)(idx >> 10);
    int h = (int)(idx & 1023);
    float s = 0.f;
    #pragma unroll
    for (int k = 0; k < TOPK; k++) {
        int   p = g_pair_of[t * TOPK + k];
        int   e = g_topk_idx[t * TOPK + k];
        float w = g_topk_w[t * TOPK + k];
        s += w * (g_y[(size_t)p * HD + h] + db[(size_t)e * HD + h]);
    }
    out[(size_t)t * HD + h] = s;
}

// -------- launch --------
extern "C" void kernel_launch(void* const* d_in, const int* in_sizes, int n_in,
                              void* d_out, int out_size) {
    const float* hidden  = (const float*)d_in[0];
    const float* gate_up = (const float*)d_in[1];
    const float* gub     = (const float*)d_in[2];
    const float* down    = (const float*)d_in[3];
    const float* db      = (const float*)d_in[4];
    const float* rw      = (const float*)d_in[5];
    const float* rb      = (const float*)d_in[6];

    float* out_routed = (float*)d_out;
    float* out_scores = (float*)d_out + (size_t)TOK * HD;

    static bool attr_done = false;
    if (!attr_done) {
        cudaFuncSetAttribute(moe_gemm<true>,  cudaFuncAttributeMaxDynamicSharedMemorySize, SMEM_BYTES);
        cudaFuncSetAttribute(moe_gemm<false>, cudaFuncAttributeMaxDynamicSharedMemorySize, SMEM_BYTES);
        attr_done = true;
    }

    reset_kernel<<<1, 32>>>();
    router_kernel<<<TOK, 256>>>(hidden, rw, rb, out_scores);
    prefix_kernel<<<1, 32>>>();
    scatter_kernel<<<(TOK + 255) / 256, 256>>>();

    moe_gemm<true><<<dim3(8, NE * 16), 512, SMEM_BYTES>>>(hidden, gate_up, gub);
    moe_gemm<false><<<dim3(4, NE * 16), 512, SMEM_BYTES>>>(nullptr, down, nullptr);
    combine_kernel<<<((size_t)TOK * HD + 255) / 256, 256>>>(db, out_routed);
}

// round 5
// speedup vs baseline: 1.2266x; 1.2266x over previous
#include <cuda_runtime.h>
#include <math.h>
#include <stdint.h>

#define TOK   2048
#define HD    1024
#define ID    1024
#define NE    32
#define TOPK  4
#define TWOI  2048
#define PAIRS (TOK*TOPK)
#define LIMITF 7.0f
#define ALPHAF 1.702f

// -------- device scratch --------
__device__ int   g_count[NE];
__device__ int   g_offset[NE];
__device__ int   g_cursor[NE];
__device__ int   g_topk_idx[TOK * TOPK];
__device__ float g_topk_w[TOK * TOPK];
__device__ int   g_pair_token[PAIRS];
__device__ int   g_pair_of[TOK * TOPK];
__device__ float g_act[(size_t)PAIRS * ID];
__device__ float g_y[(size_t)PAIRS * HD];

// -------- helpers --------
__device__ __forceinline__ float tfr(float x) {   // fp32 -> tf32 (rna), fp32 container
    unsigned r;
    asm("cvt.rna.tf32.f32 %0, %1;" : "=r"(r) : "f"(x));
    return __uint_as_float(r);
}
__device__ __forceinline__ float4 tfr4(float4 v) {
    return make_float4(tfr(v.x), tfr(v.y), tfr(v.z), tfr(v.w));
}

__device__ __forceinline__ void mma_tf32(float* d, const unsigned* a, const unsigned* b) {
    asm volatile(
        "mma.sync.aligned.m16n8k8.row.col.f32.tf32.tf32.f32 "
        "{%0,%1,%2,%3}, {%4,%5,%6,%7}, {%8,%9}, {%0,%1,%2,%3};\n"
        : "+f"(d[0]), "+f"(d[1]), "+f"(d[2]), "+f"(d[3])
        : "r"(a[0]), "r"(a[1]), "r"(a[2]), "r"(a[3]),
          "r"(b[0]), "r"(b[1]));
}

// -------- grouped tf32 GEMM (both stages), 256 thr, 128x128 tile, BK=16 --------
// FIRST:  A = gathered x rows, W = gate_up (ldb=2048), out = g_act (fused act)
// !FIRST: A = g_act rows,      W = down    (ldb=1024), out = g_y
template<bool FIRST>
__global__ __launch_bounds__(256, 2) void moe_gemm(const float* __restrict__ x,
                                                   const float* __restrict__ W,
                                                   const float* __restrict__ gub) {
    const int LDBW = FIRST ? TWOI : HD;
    const int bx = blockIdx.x;
    const int e  = blockIdx.y >> 4;
    const int rt = blockIdx.y & 15;
    const int base = g_offset[e];
    const int cnt  = g_count[e];
    const int row0 = rt * 128;
    if (row0 >= cnt) return;

    __shared__ float As[2][128][20];   // [m][k], pad 4 (proven conflict-free frag loads)
    __shared__ float Bs[2][16][132];   // [k][n], pad 4

    const int tid  = threadIdx.x;
    const int lane = tid & 31;
    const int wid  = tid >> 5;
    const int wm   = wid >> 2;         // 0..1
    const int wn   = wid & 3;          // 0..3
    const int lr   = lane >> 2;        // 0..7
    const int lc   = lane & 3;         // 0..3

    // A staging: thread -> (row tid>>1, k-half tid&1): 8 floats = 2 LDG.128 / 2 STS.128
    const int rowA  = tid >> 1;
    const int halfA = (tid & 1) * 8;
    int ar = row0 + rowA; if (ar >= cnt) ar = cnt - 1;
    const float* aRow;
    if (FIRST) aRow = x + (size_t)g_pair_token[base + ar] * HD + halfA;
    else       aRow = (const float*)g_act + (size_t)(base + ar) * ID + halfA;

    // B staging: thread -> (k row tid>>4, n octet tid&15): 8 floats
    const int kB = tid >> 4;
    const int nB = (tid & 15) * 8;
    const float* bRow = W + ((size_t)e * 1024 + kB) * LDBW + bx * 128 + nB;

    float acc[4][4][4];
    #pragma unroll
    for (int i = 0; i < 4; i++)
        #pragma unroll
        for (int j = 0; j < 4; j++)
            #pragma unroll
            for (int q = 0; q < 4; q++) acc[i][j][q] = 0.f;

    // ---- prologue: tile 0 -> buf 0 ----
    {
        float4 a0 = *(const float4*)aRow;
        float4 a1 = *(const float4*)(aRow + 4);
        float4 b0 = *(const float4*)bRow;
        float4 b1 = *(const float4*)(bRow + 4);
        *(float4*)&As[0][rowA][halfA]     = tfr4(a0);
        *(float4*)&As[0][rowA][halfA + 4] = tfr4(a1);
        *(float4*)&Bs[0][kB][nB]          = tfr4(b0);
        *(float4*)&Bs[0][kB][nB + 4]      = tfr4(b1);
    }
    __syncthreads();

    const int NK = 64;   // 1024/16
    #pragma unroll 1
    for (int kt = 0; kt < NK; kt++) {
        // prefetch next tile (LDG latency hidden under the MMA section)
        float4 a0, a1, b0, b1;
        if (kt + 1 < NK) {
            const float* ap = aRow + (kt + 1) * 16;
            a0 = *(const float4*)ap;
            a1 = *(const float4*)(ap + 4);
            const float* bp = bRow + (size_t)(kt + 1) * 16 * LDBW;
            b0 = *(const float4*)bp;
            b1 = *(const float4*)(bp + 4);
        }

        const int cur = kt & 1;
        #pragma unroll
        for (int kk = 0; kk < 2; kk++) {
            unsigned af[4][4];
            #pragma unroll
            for (int mt = 0; mt < 4; mt++) {
                const int r = wm * 64 + mt * 16 + lr;
                const int k = kk * 8 + lc;
                af[mt][0] = __float_as_uint(As[cur][r][k]);
                af[mt][1] = __float_as_uint(As[cur][r + 8][k]);
                af[mt][2] = __float_as_uint(As[cur][r][k + 4]);
                af[mt][3] = __float_as_uint(As[cur][r + 8][k + 4]);
            }
            #pragma unroll
            for (int nt = 0; nt < 4; nt++) {
                const int n = wn * 32 + nt * 8 + lr;
                unsigned bf[2];
                bf[0] = __float_as_uint(Bs[cur][kk * 8 + lc][n]);
                bf[1] = __float_as_uint(Bs[cur][kk * 8 + lc + 4][n]);
                #pragma unroll
                for (int mt = 0; mt < 4; mt++)
                    mma_tf32(acc[mt][nt], af[mt], bf);
            }
        }

        if (kt + 1 < NK) {
            const int nb = cur ^ 1;
            *(float4*)&As[nb][rowA][halfA]     = tfr4(a0);
            *(float4*)&As[nb][rowA][halfA + 4] = tfr4(a1);
            *(float4*)&Bs[nb][kB][nB]          = tfr4(b0);
            *(float4*)&Bs[nb][kB][nB + 4]      = tfr4(b1);
        }
        __syncthreads();
    }

    // ---- epilogue ----
    if (FIRST) {
        const float* gb = gub + (size_t)e * TWOI;
        #pragma unroll
        for (int mt = 0; mt < 4; mt++) {
            #pragma unroll
            for (int half = 0; half < 2; half++) {
                const int grow = row0 + wm * 64 + mt * 16 + lr + half * 8;
                if (grow < cnt) {
                    float* orow = g_act + (size_t)(base + grow) * ID;
                    #pragma unroll
                    for (int nt = 0; nt < 4; nt++) {
                        const int i = bx * 64 + wn * 16 + nt * 4 + lc;
                        float gate = acc[mt][nt][half * 2 + 0] + gb[2 * i];
                        float up   = acc[mt][nt][half * 2 + 1] + gb[2 * i + 1];
                        gate = fminf(gate, LIMITF);
                        up   = fminf(fmaxf(up, -LIMITF), LIMITF);
                        float glu = gate / (1.f + __expf(-gate * ALPHAF));
                        orow[i] = (up + 1.f) * glu;
                    }
                }
            }
        }
    } else {
        #pragma unroll
        for (int mt = 0; mt < 4; mt++) {
            #pragma unroll
            for (int half = 0; half < 2; half++) {
                const int grow = row0 + wm * 64 + mt * 16 + lr + half * 8;
                if (grow < cnt) {
                    float* orow = g_y + (size_t)(base + grow) * HD;
                    #pragma unroll
                    for (int nt = 0; nt < 4; nt++) {
                        const int c = bx * 128 + wn * 32 + nt * 8 + 2 * lc;
                        *(float2*)(orow + c) = make_float2(acc[mt][nt][half * 2 + 0],
                                                           acc[mt][nt][half * 2 + 1]);
                    }
                }
            }
        }
    }
}

// -------- K0: reset counters --------
__global__ void reset_kernel() {
    int i = threadIdx.x;
    if (i < NE) g_count[i] = 0;
}

// -------- K1: router --------
__global__ void router_kernel(const float* __restrict__ x,
                              const float* __restrict__ rw,
                              const float* __restrict__ rb,
                              float* __restrict__ scores_out) {
    const int t    = blockIdx.x;
    const int tid  = threadIdx.x;
    const int warp = tid >> 5;
    const int lane = tid & 31;

    __shared__ float logits[NE];
    const float* xr = x + (size_t)t * HD;

    for (int e = warp; e < NE; e += 8) {
        const float* w = rw + (size_t)e * HD;
        float s = 0.f;
        for (int h = lane; h < HD; h += 32) s += xr[h] * w[h];
        #pragma unroll
        for (int off = 16; off; off >>= 1) s += __shfl_down_sync(0xffffffffu, s, off);
        if (lane == 0) logits[e] = s + rb[e];
    }
    __syncthreads();

    if (warp == 0) {
        float cur = logits[lane];
        float sel_val[TOPK];
        int   sel_idx[TOPK];
        #pragma unroll
        for (int k = 0; k < TOPK; k++) {
            float bv = cur; int bi = lane;
            #pragma unroll
            for (int off = 16; off; off >>= 1) {
                float ov = __shfl_xor_sync(0xffffffffu, bv, off);
                int   oi = __shfl_xor_sync(0xffffffffu, bi, off);
                if (ov > bv || (ov == bv && oi < bi)) { bv = ov; bi = oi; }
            }
            sel_val[k] = bv; sel_idx[k] = bi;
            if (lane == bi) cur = -1e30f;
        }
        float m = sel_val[0];
        float ex[TOPK]; float sum = 0.f;
        #pragma unroll
        for (int k = 0; k < TOPK; k++) { ex[k] = expf(sel_val[k] - m); sum += ex[k]; }
        float inv = 1.f / sum;

        float sc = 0.f;
        #pragma unroll
        for (int k = 0; k < TOPK; k++) if (lane == sel_idx[k]) sc = ex[k] * inv;
        scores_out[(size_t)t * NE + lane] = sc;

        if (lane < TOPK) {
            g_topk_idx[t * TOPK + lane] = sel_idx[lane];
            g_topk_w[t * TOPK + lane]   = ex[lane] * inv;
            atomicAdd(&g_count[sel_idx[lane]], 1);
        }
    }
}

// -------- K2: prefix sum --------
__global__ void prefix_kernel() {
    if (threadIdx.x == 0) {
        int acc = 0;
        for (int e = 0; e < NE; e++) {
            g_offset[e] = acc;
            g_cursor[e] = acc;
            acc += g_count[e];
        }
    }
}

// -------- K3: scatter --------
__global__ void scatter_kernel() {
    int t = blockIdx.x * blockDim.x + threadIdx.x;
    if (t >= TOK) return;
    #pragma unroll
    for (int k = 0; k < TOPK; k++) {
        int e   = g_topk_idx[t * TOPK + k];
        int pos = atomicAdd(&g_cursor[e], 1);
        g_pair_token[pos] = t;
        g_pair_of[t * TOPK + k] = pos;
    }
}

// -------- K7: weighted combine + down bias --------
__global__ void combine_kernel(const float* __restrict__ db,
                               float* __restrict__ out) {
    size_t idx = (size_t)blockIdx.x * blockDim.x + threadIdx.x;
    if (idx >= (size_t)TOK * HD) return;
    int t = (int)(idx >> 10);
    int h = (int)(idx & 1023);
    float s = 0.f;
    #pragma unroll
    for (int k = 0; k < TOPK; k++) {
        int   p = g_pair_of[t * TOPK + k];
        int   e = g_topk_idx[t * TOPK + k];
        float w = g_topk_w[t * TOPK + k];
        s += w * (g_y[(size_t)p * HD + h] + db[(size_t)e * HD + h]);
    }
    out[(size_t)t * HD + h] = s;
}

// -------- launch --------
extern "C" void kernel_launch(void* const* d_in, const int* in_sizes, int n_in,
                              void* d_out, int out_size) {
    const float* hidden  = (const float*)d_in[0];
    const float* gate_up = (const float*)d_in[1];
    const float* gub     = (const float*)d_in[2];
    const float* down    = (const float*)d_in[3];
    const float* db      = (const float*)d_in[4];
    const float* rw      = (const float*)d_in[5];
    const float* rb      = (const float*)d_in[6];

    float* out_routed = (float*)d_out;
    float* out_scores = (float*)d_out + (size_t)TOK * HD;

    reset_kernel<<<1, 32>>>();
    router_kernel<<<TOK, 256>>>(hidden, rw, rb, out_scores);
    prefix_kernel<<<1, 32>>>();
    scatter_kernel<<<(TOK + 255) / 256, 256>>>();

    moe_gemm<true><<<dim3(16, NE * 16), 256>>>(hidden, gate_up, gub);
    moe_gemm<false><<<dim3(8, NE * 16), 256>>>(nullptr, down, nullptr);
    combine_kernel<<<((size_t)TOK * HD + 255) / 256, 256>>>(db, out_routed);
}

// round 7
// speedup vs baseline: 1.6153x; 1.3169x over previous
#include <cuda_runtime.h>
#include <cuda_fp16.h>
#include <math.h>
#include <stdint.h>

#define TOK   2048
#define HD    1024
#define ID    1024
#define NE    32
#define TOPK  4
#define TWOI  2048
#define PAIRS (TOK*TOPK)
#define LIMITF 7.0f
#define ALPHAF 1.702f

// -------- device scratch --------
__device__ int   g_count[NE];
__device__ int   g_offset[NE];
__device__ int   g_cursor[NE];
__device__ int   g_topk_idx[TOK * TOPK];
__device__ float g_topk_w[TOK * TOPK];
__device__ int   g_pair_token[PAIRS];
__device__ int   g_pair_of[TOK * TOPK];
__device__ float g_act[(size_t)PAIRS * ID];
__device__ float g_y[(size_t)PAIRS * HD];

// -------- helpers --------
__device__ __forceinline__ void mma_f16(float* d, const uint32_t* a, const uint32_t* b) {
    asm volatile(
        "mma.sync.aligned.m16n8k16.row.col.f32.f16.f16.f32 "
        "{%0,%1,%2,%3}, {%4,%5,%6,%7}, {%8,%9}, {%0,%1,%2,%3};\n"
        : "+f"(d[0]), "+f"(d[1]), "+f"(d[2]), "+f"(d[3])
        : "r"(a[0]), "r"(a[1]), "r"(a[2]), "r"(a[3]),
          "r"(b[0]), "r"(b[1]));
}
__device__ __forceinline__ uint32_t h2u(__half2 h) { return *(uint32_t*)&h; }
__device__ __forceinline__ uint4 f8_to_h8(float4 v0, float4 v1) {
    uint4 u;
    u.x = h2u(__floats2half2_rn(v0.x, v0.y));
    u.y = h2u(__floats2half2_rn(v0.z, v0.w));
    u.z = h2u(__floats2half2_rn(v1.x, v1.y));
    u.w = h2u(__floats2half2_rn(v1.z, v1.w));
    return u;
}
__device__ __forceinline__ uint4 pack8(const float* v) {
    uint4 u;
    u.x = h2u(__floats2half2_rn(v[0], v[1]));
    u.y = h2u(__floats2half2_rn(v[2], v[3]));
    u.z = h2u(__floats2half2_rn(v[4], v[5]));
    u.w = h2u(__floats2half2_rn(v[6], v[7]));
    return u;
}

// -------- grouped fp16 GEMM (both stages), 256 thr, 128x128 tile, BK=16 --------
// A smem [m][k] padded to 24 halves/row; B smem TRANSPOSED [n][k] padded same.
template<bool FIRST>
__global__ __launch_bounds__(256, 2) void moe_gemm(const float* __restrict__ x,
                                                   const float* __restrict__ W,
                                                   const float* __restrict__ gub) {
    const int LDBW = FIRST ? TWOI : HD;
    const int bx = blockIdx.x;
    const int e  = blockIdx.y >> 4;
    const int rt = blockIdx.y & 15;
    const int base = g_offset[e];
    const int cnt  = g_count[e];
    const int row0 = rt * 128;
    if (row0 >= cnt) return;

    __shared__ __align__(16) __half As[2][128][24];
    __shared__ __align__(16) __half Bs[2][128][24];   // [n][k]

    const int tid  = threadIdx.x;
    const int lane = tid & 31;
    const int wid  = tid >> 5;
    const int wm   = wid >> 2;         // 0..1
    const int wn   = wid & 3;          // 0..3
    const int lr   = lane >> 2;        // 0..7
    const int lc   = lane & 3;         // 0..3

    // A staging: thread -> (m row tid>>1, k-half (tid&1)*8)
    const int rowA  = tid >> 1;
    const int halfA = (tid & 1) * 8;
    int ar = row0 + rowA; if (ar >= cnt) ar = cnt - 1;
    const float* aRow;
    if (FIRST) aRow = x + (size_t)g_pair_token[base + ar] * HD + halfA;
    else       aRow = (const float*)g_act + (size_t)(base + ar) * ID + halfA;

    // B staging: thread -> (n col tid>>1, k-half (tid&1)*8); strided column loads
    const int nB  = tid >> 1;
    const int khB = (tid & 1) * 8;
    const float* bCol = W + ((size_t)e * 1024 + khB) * LDBW + bx * 128 + nB;

    float acc[4][4][4];
    #pragma unroll
    for (int i = 0; i < 4; i++)
        #pragma unroll
        for (int j = 0; j < 4; j++)
            #pragma unroll
            for (int q = 0; q < 4; q++) acc[i][j][q] = 0.f;

    // ---- prologue: tile 0 -> buf 0 ----
    {
        float4 a0 = *(const float4*)aRow;
        float4 a1 = *(const float4*)(aRow + 4);
        float bv[8];
        #pragma unroll
        for (int j = 0; j < 8; j++) bv[j] = bCol[(size_t)j * LDBW];
        *(uint4*)&As[0][rowA][halfA] = f8_to_h8(a0, a1);
        *(uint4*)&Bs[0][nB][khB]     = pack8(bv);
    }
    __syncthreads();

    const int NK = 64;   // 1024/16
    #pragma unroll 1
    for (int kt = 0; kt < NK; kt++) {
        // prefetch next tile into registers
        float4 a0, a1;
        float bv[8];
        if (kt + 1 < NK) {
            const float* ap = aRow + (kt + 1) * 16;
            a0 = *(const float4*)ap;
            a1 = *(const float4*)(ap + 4);
            #pragma unroll
            for (int j = 0; j < 8; j++)
                bv[j] = bCol[(size_t)((kt + 1) * 16 + j) * LDBW];
        }

        const int cur = kt & 1;

        // B fragments: half2 loads from [n][k] layout (conflict-free)
        uint32_t bf[4][2];
        #pragma unroll
        for (int nt = 0; nt < 4; nt++) {
            const int n = wn * 32 + nt * 8 + lr;
            bf[nt][0] = *(const uint32_t*)&Bs[cur][n][2 * lc];
            bf[nt][1] = *(const uint32_t*)&Bs[cur][n][2 * lc + 8];
        }
        #pragma unroll
        for (int mt = 0; mt < 4; mt++) {
            const int r = wm * 64 + mt * 16 + lr;
            uint32_t af[4];
            af[0] = *(const uint32_t*)&As[cur][r][2 * lc];
            af[1] = *(const uint32_t*)&As[cur][r + 8][2 * lc];
            af[2] = *(const uint32_t*)&As[cur][r][2 * lc + 8];
            af[3] = *(const uint32_t*)&As[cur][r + 8][2 * lc + 8];
            #pragma unroll
            for (int nt = 0; nt < 4; nt++)
                mma_f16(acc[mt][nt], af, bf[nt]);
        }

        if (kt + 1 < NK) {
            const int nb = (kt + 1) & 1;
            *(uint4*)&As[nb][rowA][halfA] = f8_to_h8(a0, a1);
            *(uint4*)&Bs[nb][nB][khB]     = pack8(bv);
        }
        __syncthreads();
    }

    // ---- epilogue (same acc fragment layout as m16n8k8) ----
    if (FIRST) {
        const float* gb = gub + (size_t)e * TWOI;
        #pragma unroll
        for (int mt = 0; mt < 4; mt++) {
            #pragma unroll
            for (int half = 0; half < 2; half++) {
                const int grow = row0 + wm * 64 + mt * 16 + lr + half * 8;
                if (grow < cnt) {
                    float* orow = g_act + (size_t)(base + grow) * ID;
                    #pragma unroll
                    for (int nt = 0; nt < 4; nt++) {
                        const int i = bx * 64 + wn * 16 + nt * 4 + lc;
                        float gate = acc[mt][nt][half * 2 + 0] + gb[2 * i];
                        float up   = acc[mt][nt][half * 2 + 1] + gb[2 * i + 1];
                        gate = fminf(gate, LIMITF);
                        up   = fminf(fmaxf(up, -LIMITF), LIMITF);
                        float glu = gate / (1.f + __expf(-gate * ALPHAF));
                        orow[i] = (up + 1.f) * glu;
                    }
                }
            }
        }
    } else {
        #pragma unroll
        for (int mt = 0; mt < 4; mt++) {
            #pragma unroll
            for (int half = 0; half < 2; half++) {
                const int grow = row0 + wm * 64 + mt * 16 + lr + half * 8;
                if (grow < cnt) {
                    float* orow = g_y + (size_t)(base + grow) * HD;
                    #pragma unroll
                    for (int nt = 0; nt < 4; nt++) {
                        const int c = bx * 128 + wn * 32 + nt * 8 + 2 * lc;
                        *(float2*)(orow + c) = make_float2(acc[mt][nt][half * 2 + 0],
                                                           acc[mt][nt][half * 2 + 1]);
                    }
                }
            }
        }
    }
}

// -------- K0: reset counters --------
__global__ void reset_kernel() {
    int i = threadIdx.x;
    if (i < NE) g_count[i] = 0;
}

// -------- K1: router --------
__global__ void router_kernel(const float* __restrict__ x,
                              const float* __restrict__ rw,
                              const float* __restrict__ rb,
                              float* __restrict__ scores_out) {
    const int t    = blockIdx.x;
    const int tid  = threadIdx.x;
    const int warp = tid >> 5;
    const int lane = tid & 31;

    __shared__ float logits[NE];
    const float* xr = x + (size_t)t * HD;

    for (int e = warp; e < NE; e += 8) {
        const float* w = rw + (size_t)e * HD;
        float s = 0.f;
        for (int h = lane; h < HD; h += 32) s += xr[h] * w[h];
        #pragma unroll
        for (int off = 16; off; off >>= 1) s += __shfl_down_sync(0xffffffffu, s, off);
        if (lane == 0) logits[e] = s + rb[e];
    }
    __syncthreads();

    if (warp == 0) {
        float cur = logits[lane];
        float sel_val[TOPK];
        int   sel_idx[TOPK];
        #pragma unroll
        for (int k = 0; k < TOPK; k++) {
            float bv = cur; int bi = lane;
            #pragma unroll
            for (int off = 16; off; off >>= 1) {
                float ov = __shfl_xor_sync(0xffffffffu, bv, off);
                int   oi = __shfl_xor_sync(0xffffffffu, bi, off);
                if (ov > bv || (ov == bv && oi < bi)) { bv = ov; bi = oi; }
            }
            sel_val[k] = bv; sel_idx[k] = bi;
            if (lane == bi) cur = -1e30f;
        }
        float m = sel_val[0];
        float ex[TOPK]; float sum = 0.f;
        #pragma unroll
        for (int k = 0; k < TOPK; k++) { ex[k] = expf(sel_val[k] - m); sum += ex[k]; }
        float inv = 1.f / sum;

        float sc = 0.f;
        #pragma unroll
        for (int k = 0; k < TOPK; k++) if (lane == sel_idx[k]) sc = ex[k] * inv;
        scores_out[(size_t)t * NE + lane] = sc;

        if (lane < TOPK) {
            g_topk_idx[t * TOPK + lane] = sel_idx[lane];
            g_topk_w[t * TOPK + lane]   = ex[lane] * inv;
            atomicAdd(&g_count[sel_idx[lane]], 1);
        }
    }
}

// -------- K2: prefix sum --------
__global__ void prefix_kernel() {
    if (threadIdx.x == 0) {
        int acc = 0;
        for (int e = 0; e < NE; e++) {
            g_offset[e] = acc;
            g_cursor[e] = acc;
            acc += g_count[e];
        }
    }
}

// -------- K3: scatter --------
__global__ void scatter_kernel() {
    int t = blockIdx.x * blockDim.x + threadIdx.x;
    if (t >= TOK) return;
    #pragma unroll
    for (int k = 0; k < TOPK; k++) {
        int e   = g_topk_idx[t * TOPK + k];
        int pos = atomicAdd(&g_cursor[e], 1);
        g_pair_token[pos] = t;
        g_pair_of[t * TOPK + k] = pos;
    }
}

// -------- K7: weighted combine + down bias --------
__global__ void combine_kernel(const float* __restrict__ db,
                               float* __restrict__ out) {
    size_t idx = (size_t)blockIdx.x * blockDim.x + threadIdx.x;
    if (idx >= (size_t)TOK * HD) return;
    int t = (int)(idx >> 10);
    int h = (int)(idx & 1023);
    float s = 0.f;
    #pragma unroll
    for (int k = 0; k < TOPK; k++) {
        int   p = g_pair_of[t * TOPK + k];
        int   e = g_topk_idx[t * TOPK + k];
        float w = g_topk_w[t * TOPK + k];
        s += w * (g_y[(size_t)p * HD + h] + db[(size_t)e * HD + h]);
    }
    out[(size_t)t * HD + h] = s;
}

// -------- launch --------
extern "C" void kernel_launch(void* const* d_in, const int* in_sizes, int n_in,
                              void* d_out, int out_size) {
    const float* hidden  = (const float*)d_in[0];
    const float* gate_up = (const float*)d_in[1];
    const float* gub     = (const float*)d_in[2];
    const float* down    = (const float*)d_in[3];
    const float* db      = (const float*)d_in[4];
    const float* rw      = (const float*)d_in[5];
    const float* rb      = (const float*)d_in[6];

    float* out_routed = (float*)d_out;
    float* out_scores = (float*)d_out + (size_t)TOK * HD;

    reset_kernel<<<1, 32>>>();
    router_kernel<<<TOK, 256>>>(hidden, rw, rb, out_scores);
    prefix_kernel<<<1, 32>>>();
    scatter_kernel<<<(TOK + 255) / 256, 256>>>();

    moe_gemm<true><<<dim3(16, NE * 16), 256>>>(hidden, gate_up, gub);
    moe_gemm<false><<<dim3(8, NE * 16), 256>>>(nullptr, down, nullptr);
    combine_kernel<<<((size_t)TOK * HD + 255) / 256, 256>>>(db, out_routed);
}